// round 13
// baseline (speedup 1.0000x reference)
#include <cuda_runtime.h>
#include <cuda_bf16.h>
#include <math.h>

#define TT  512
#define BB  64
#define DIN 256
#define NN  1024
#define OO  128

// ---------------- device scratch (no cudaMalloc allowed) ----------------
__device__ float    g_xw[(TT - 1) * BB * NN];   // [t][b][n], t = 0..510 feeds step t+1
__device__ float    g_sbuf[4 * NN * BB];        // 4-deep ring, [slot][n][b]
__device__ float    g_part[16 * 8 * 4096];      // [ntile][src_kq][b*64+c]
__device__ unsigned g_pub[16][8];               // partial-published flag per (ntile, src) — 32B sector per ntile
__device__ unsigned g_dn[16][8];                // step-done flag per (ntile, kq)       — 32B sector per ntile

// ---------------- sync helpers ----------------
__device__ __forceinline__ unsigned ld_acq(const unsigned* p) {
    unsigned v;
    asm volatile("ld.acquire.gpu.u32 %0, [%1];" : "=r"(v) : "l"(p));
    return v;
}
__device__ __forceinline__ void st_rel(unsigned* p, unsigned v) {
    asm volatile("st.release.gpu.u32 [%0], %1;" :: "l"(p), "r"(v) : "memory");
}
// spin until all 8 flags of one sector >= tgt. TID0-ONLY (then __syncthreads):
// many-thread gpu-scope polling has caused watchdog kills (R4/R5/R11).
__device__ __forceinline__ void spin_sector(const unsigned* f, unsigned tgt) {
    #pragma unroll 1
    for (int it = 0; ; it++) {
        bool ok = true;
        #pragma unroll
        for (int i = 0; i < 8; i++) ok &= (ld_acq(f + i) >= tgt);
        if (ok) return;
        if (it >= 256) __nanosleep(64);
    }
}
__device__ __forceinline__ void spin_2sector(const unsigned* fa, const unsigned* fb,
                                             unsigned tgt) {
    #pragma unroll 1
    for (int it = 0; ; it++) {
        bool ok = true;
        #pragma unroll
        for (int i = 0; i < 8; i++) ok &= (ld_acq(fa + i) >= tgt);
        #pragma unroll
        for (int i = 0; i < 8; i++) ok &= (ld_acq(fb + i) >= tgt);
        if (ok) return;
        if (it >= 256) __nanosleep(64);
    }
}

// packed fp32x2 FMA: d = a*b + d (lane-wise fp32, exact FFMA numerics)
__device__ __forceinline__ void ffma2(unsigned long long& d,
                                      unsigned long long a, unsigned long long b) {
    asm("fma.rn.f32x2 %0, %1, %2, %0;" : "+l"(d) : "l"(a), "l"(b));
}

// ---------------- init: reset flags, zero s[:,0,:] ----------------
__global__ void init_kernel(float* __restrict__ sout) {
    int idx = blockIdx.x * blockDim.x + threadIdx.x;
    if (idx < 128) { (&g_pub[0][0])[idx] = 0; (&g_dn[0][0])[idx] = 0; }
    if (idx < NN * BB) {
        g_sbuf[idx] = 0.0f;                          // ring slot 0 = state t=0
        int b = idx / NN, n = idx % NN;
        sout[((size_t)b * TT + 0) * NN + n] = 0.0f;  // s[:,0,:] = 0
    }
}

// ---------------- XW = X[:,t,:] @ Win, stored [t][b][n] (FFMA2 core) ----------------
// grid (511, 16), block 256. tile 64b x 64n, K=256 in chunks of 16. thread tile 4b x 4n.
__global__ void xw_kernel(const float* __restrict__ X, const float* __restrict__ Win) {
    const int t  = blockIdx.x;          // 0..510
    const int c0 = blockIdx.y * 64;
    __shared__ float xs[16][64];        // [d][b]
    __shared__ float ws[16][128];       // [d][64 cols dup (w,w)]
    const int tid = threadIdx.x;
    const int bg  = tid & 15;           // b rows bg*4..+3
    const int ng  = tid >> 4;           // cols ng*4..+3 (0..15)
    unsigned long long ap[4][2] = {};

    for (int d0 = 0; d0 < DIN; d0 += 16) {
        {
            int b  = tid & 63;
            int d4 = (tid >> 6) * 4;
            float4 xv = *(const float4*)&X[((size_t)b * TT + t) * DIN + d0 + d4];
            xs[d4 + 0][b] = xv.x; xs[d4 + 1][b] = xv.y;
            xs[d4 + 2][b] = xv.z; xs[d4 + 3][b] = xv.w;
        }
        {
            int dr = tid >> 4;          // 0..15
            int c4 = (tid & 15) * 4;
            float4 w = *(const float4*)&Win[(size_t)(d0 + dr) * NN + c0 + c4];
            float* d = &ws[dr][(tid & 15) * 8];
            *(float4*)&d[0] = make_float4(w.x, w.x, w.y, w.y);
            *(float4*)&d[4] = make_float4(w.z, w.z, w.w, w.w);
        }
        __syncthreads();
        #pragma unroll
        for (int d = 0; d < 16; d++) {
            ulonglong2 a2  = *(const ulonglong2*)&xs[d][bg * 4];
            ulonglong2 b2a = *(const ulonglong2*)&ws[d][ng * 8];
            ffma2(ap[0][0], a2.x, b2a.x);
            ffma2(ap[0][1], a2.y, b2a.x);
            ffma2(ap[1][0], a2.x, b2a.y);
            ffma2(ap[1][1], a2.y, b2a.y);
            ulonglong2 b2b = *(const ulonglong2*)&ws[d][ng * 8 + 4];
            ffma2(ap[2][0], a2.x, b2b.x);
            ffma2(ap[2][1], a2.y, b2b.x);
            ffma2(ap[3][0], a2.x, b2b.y);
            ffma2(ap[3][1], a2.y, b2b.y);
        }
        __syncthreads();
    }
    #pragma unroll
    for (int i = 0; i < 4; i++) {
        int hi = i >> 1;
        float4 v; float2 u;
        u = *(float2*)&ap[0][hi]; v.x = (i & 1) ? u.y : u.x;
        u = *(float2*)&ap[1][hi]; v.y = (i & 1) ? u.y : u.x;
        u = *(float2*)&ap[2][hi]; v.z = (i & 1) ? u.y : u.x;
        u = *(float2*)&ap[3][hi]; v.w = (i & 1) ? u.y : u.x;
        *(float4*)&g_xw[((size_t)t * BB + bg * 4 + i) * NN + c0 + ng * 4] = v;
    }
}

// ---------------- persistent recurrence kernel ----------------
// 128 blocks x 128 threads, 1 block/SM. block = (ntile X 0..15, kq 0..7).
// Block GEMM tile: 64b x 64c over K rows [kq*128, +128). Thread tile 4b x 8c.
// All 8 blocks of a ntile publish partials; each finalizes its own 8-col slice.
// All gpu-scope waits: tid0 polls flag sectors, then __syncthreads.
// dynamic smem: wsm float[128][128] dup (64KB) | ssm float[2][32*64] (16KB)
#define RNN_SMEM (65536 + 16384)

__global__ void __launch_bounds__(128, 1) rnn_kernel(const float* __restrict__ W,
                                                     float* __restrict__ sout) {
    extern __shared__ char smem_raw[];
    float* wsm = (float*)smem_raw;                 // [k(128)][128 = 64 cols dup (w,w)]
    float* ssm = (float*)(smem_raw + 65536);       // [buf(2)][k(32)*b(64)]

    const int bx  = blockIdx.x;
    const int X   = bx >> 3;            // ntile 0..15 (64 cols)
    const int kq  = bx & 7;             // K-split 0..7 (128 rows)
    const int c0  = X * 64;
    const int kbase = kq * 128;
    const int tid = threadIdx.x;
    const int bg  = tid & 15;           // b-group: rows bg*4..+3
    const int ng  = tid >> 4;           // c-group 0..7: cols ng*8..+7

    // ---- preload W slice (128 k x 64 c), duplicated pairs ----
    #pragma unroll 1
    for (int i = tid; i < 128 * 16; i += 128) {
        int k = i >> 4, g = i & 15;     // g = group of 4 cols
        float4 w = *(const float4*)&W[(size_t)(kbase + k) * NN + c0 + g * 4];
        float* d = &wsm[k * 128 + g * 8];
        *(float4*)&d[0] = make_float4(w.x, w.x, w.y, w.y);
        *(float4*)&d[4] = make_float4(w.z, w.z, w.w, w.w);
    }
    __syncthreads();

    const int n_left  = 2 * kq;         // ntile producing K rows [kq*128, +64)
    const int n_right = 2 * kq + 1;     // ntile producing [kq*128+64, +64)

    for (int t = 1; t < TT; t++) {
        // ---- head wait: inputs ready (producers done with step t-1) ----
        if (tid == 0) spin_2sector(g_dn[n_left], g_dn[n_right], (unsigned)(t - 1));
        __syncthreads();

        const float* __restrict__ sprev =
            &g_sbuf[((t - 1) & 3) * (NN * BB) + (size_t)kbase * BB];

        unsigned long long ap[8][2];    // [col][b-pair]
        #pragma unroll
        for (int j = 0; j < 8; j++) { ap[j][0] = 0ull; ap[j][1] = 0ull; }

        // prologue: chunk 0 (32 k x 64 b = 8KB) into buf 0
        {
            const float4* sv = (const float4*)sprev;
            float4* d = (float4*)ssm;
            #pragma unroll
            for (int i = 0; i < 4; i++) d[tid + 128 * i] = sv[tid + 128 * i];
        }
        __syncthreads();

        #pragma unroll 1
        for (int ch = 0; ch < 4; ch++) {
            const int buf = ch & 1;
            float4 pfs[4];
            if (ch < 3) {
                const float4* sv = (const float4*)(sprev + (size_t)(ch + 1) * 32 * BB);
                #pragma unroll
                for (int i = 0; i < 4; i++) pfs[i] = sv[tid + 128 * i];
            }
            const float* sb = ssm + buf * (32 * 64);
            const float* wr = wsm + (size_t)ch * 32 * 128 + ng * 16;
            #pragma unroll
            for (int k = 0; k < 32; k++) {
                ulonglong2 a2 = *(const ulonglong2*)&sb[k * 64 + bg * 4];  // (s0,s1),(s2,s3)
                #pragma unroll
                for (int j4 = 0; j4 < 4; j4++) {
                    ulonglong2 b2 = *(const ulonglong2*)&wr[k * 128 + j4 * 4]; // (w,w),(w',w')
                    ffma2(ap[j4 * 2 + 0][0], a2.x, b2.x);
                    ffma2(ap[j4 * 2 + 0][1], a2.y, b2.x);
                    ffma2(ap[j4 * 2 + 1][0], a2.x, b2.y);
                    ffma2(ap[j4 * 2 + 1][1], a2.y, b2.y);
                }
            }
            if (ch < 3) {
                float4* d = (float4*)(ssm + (buf ^ 1) * (32 * 64));
                #pragma unroll
                for (int i = 0; i < 4; i++) d[tid + 128 * i] = pfs[i];
                __syncthreads();
            }
        }

        // ---- g_part WAR guard (overlapped behind GEMM; usually instant):
        //      all siblings of ntile X must have finished step t-1 finalize ----
        if (tid == 0) spin_sector(g_dn[X], (unsigned)(t - 1));
        __syncthreads();

        // ---- publish partial tile (64x64) ----
        {
            float* p = &g_part[((size_t)X * 8 + kq) * 4096];
            #pragma unroll
            for (int i = 0; i < 4; i++) {           // b row = bg*4 + i
                int hi = i >> 1;
                float4 v0, v1;
                float2 u;
                u = *(float2*)&ap[0][hi]; v0.x = (i & 1) ? u.y : u.x;
                u = *(float2*)&ap[1][hi]; v0.y = (i & 1) ? u.y : u.x;
                u = *(float2*)&ap[2][hi]; v0.z = (i & 1) ? u.y : u.x;
                u = *(float2*)&ap[3][hi]; v0.w = (i & 1) ? u.y : u.x;
                u = *(float2*)&ap[4][hi]; v1.x = (i & 1) ? u.y : u.x;
                u = *(float2*)&ap[5][hi]; v1.y = (i & 1) ? u.y : u.x;
                u = *(float2*)&ap[6][hi]; v1.z = (i & 1) ? u.y : u.x;
                u = *(float2*)&ap[7][hi]; v1.w = (i & 1) ? u.y : u.x;
                int b = bg * 4 + i;
                *(float4*)&p[b * 64 + ng * 8 + 0] = v0;
                *(float4*)&p[b * 64 + ng * 8 + 4] = v1;
            }
        }
        __threadfence();
        __syncthreads();
        if (tid == 0) st_rel(&g_pub[X][kq], (unsigned)t);

        // ---- finalize our 8-col slice ----
        const int bfin = tid >> 1;                      // b 0..63
        const int cloc = kq * 8 + (tid & 1) * 4;        // col within ntile
        // prefetch xw operand (g_xw constant during rnn) to overlap the wait
        float4 xv = *(const float4*)&g_xw[((size_t)(t - 1) * BB + bfin) * NN + c0 + cloc];
        if (tid == 0) spin_sector(g_pub[X], (unsigned)t);
        __syncthreads();
        {
            float4 sum = make_float4(0.f, 0.f, 0.f, 0.f);
            #pragma unroll
            for (int src = 0; src < 8; src++) {
                float4 v = *(const float4*)&g_part[((size_t)X * 8 + src) * 4096 + bfin * 64 + cloc];
                sum.x += v.x; sum.y += v.y; sum.z += v.z; sum.w += v.w;
            }
            float4 sn;
            sn.x = tanhf(sum.x + xv.x);
            sn.y = tanhf(sum.y + xv.y);
            sn.z = tanhf(sum.z + xv.z);
            sn.w = tanhf(sum.w + xv.w);
            // state ring [slot][n][b]
            float* sb = &g_sbuf[(t & 3) * (NN * BB)];
            sb[(size_t)(c0 + cloc + 0) * BB + bfin] = sn.x;
            sb[(size_t)(c0 + cloc + 1) * BB + bfin] = sn.y;
            sb[(size_t)(c0 + cloc + 2) * BB + bfin] = sn.z;
            sb[(size_t)(c0 + cloc + 3) * BB + bfin] = sn.w;
            __threadfence();
            __syncthreads();
            if (tid == 0) st_rel(&g_dn[X][kq], (unsigned)t);
            // sout write AFTER the done-flag: nothing in rnn reads it; kernel-end
            // ordering guarantees visibility for out_kernel.
            *(float4*)&sout[((size_t)bfin * TT + t) * NN + c0 + cloc] = sn;
        }
    }
}

// ---------------- out = s @ Wout + bout (FFMA2 core) ----------------
// grid (512, 2), block 256. tile 64m x 64o, K=1024 chunks of 16. thread tile 4m x 4o.
__global__ void out_kernel(const float* __restrict__ s, const float* __restrict__ Wout,
                           const float* __restrict__ bout, float* __restrict__ out) {
    const int m0 = blockIdx.x * 64;
    const int c0 = blockIdx.y * 64;
    __shared__ float as[16][64];        // [k][m]
    __shared__ float ws[16][128];       // [k][64 cols dup (w,w)]
    const int tid = threadIdx.x;
    const int bg  = tid & 15;           // m rows bg*4..+3
    const int ng  = tid >> 4;           // cols ng*4..+3 (0..15)
    unsigned long long ap[4][2] = {};

    for (int k0 = 0; k0 < NN; k0 += 16) {
        {
            int m  = tid & 63;
            int k4 = (tid >> 6) * 4;
            float4 v = *(const float4*)&s[(size_t)(m0 + m) * NN + k0 + k4];
            as[k4 + 0][m] = v.x; as[k4 + 1][m] = v.y;
            as[k4 + 2][m] = v.z; as[k4 + 3][m] = v.w;
        }
        {
            int kr = tid >> 4;
            int c4 = (tid & 15) * 4;
            float4 w = *(const float4*)&Wout[(size_t)(k0 + kr) * OO + c0 + c4];
            float* d = &ws[kr][(tid & 15) * 8];
            *(float4*)&d[0] = make_float4(w.x, w.x, w.y, w.y);
            *(float4*)&d[4] = make_float4(w.z, w.z, w.w, w.w);
        }
        __syncthreads();
        #pragma unroll
        for (int k = 0; k < 16; k++) {
            ulonglong2 a2  = *(const ulonglong2*)&as[k][bg * 4];
            ulonglong2 b2a = *(const ulonglong2*)&ws[k][ng * 8];
            ffma2(ap[0][0], a2.x, b2a.x);
            ffma2(ap[0][1], a2.y, b2a.x);
            ffma2(ap[1][0], a2.x, b2a.y);
            ffma2(ap[1][1], a2.y, b2a.y);
            ulonglong2 b2b = *(const ulonglong2*)&ws[k][ng * 8 + 4];
            ffma2(ap[2][0], a2.x, b2b.x);
            ffma2(ap[2][1], a2.y, b2b.x);
            ffma2(ap[3][0], a2.x, b2b.y);
            ffma2(ap[3][1], a2.y, b2b.y);
        }
        __syncthreads();
    }
    float4 bv = *(const float4*)&bout[c0 + ng * 4];
    #pragma unroll
    for (int i = 0; i < 4; i++) {
        int hi = i >> 1;
        float4 v; float2 u;
        u = *(float2*)&ap[0][hi]; v.x = ((i & 1) ? u.y : u.x) + bv.x;
        u = *(float2*)&ap[1][hi]; v.y = ((i & 1) ? u.y : u.x) + bv.y;
        u = *(float2*)&ap[2][hi]; v.z = ((i & 1) ? u.y : u.x) + bv.z;
        u = *(float2*)&ap[3][hi]; v.w = ((i & 1) ? u.y : u.x) + bv.w;
        *(float4*)&out[(size_t)(m0 + bg * 4 + i) * OO + c0 + ng * 4] = v;
    }
}

// ---------------- launch (stateless) ----------------
extern "C" void kernel_launch(void* const* d_in, const int* in_sizes, int n_in,
                              void* d_out, int out_size) {
    const float* X    = (const float*)d_in[0];  // [B,T,DIN]
    const float* Win  = (const float*)d_in[1];  // [DIN,N]
    const float* W    = (const float*)d_in[2];  // [N,N]
    const float* Wout = (const float*)d_in[3];  // [N,O]
    const float* bout = (const float*)d_in[4];  // [O]

    float* s_out = (float*)d_out;                            // [B,T,N]
    float* o_out = (float*)d_out + (size_t)BB * TT * NN;     // [B,T,O]

    cudaFuncSetAttribute(rnn_kernel, cudaFuncAttributeMaxDynamicSharedMemorySize, RNN_SMEM);

    init_kernel<<<256, 256>>>(s_out);
    xw_kernel<<<dim3(TT - 1, 16), 256>>>(X, Win);
    rnn_kernel<<<128, 128, RNN_SMEM>>>(W, s_out);
    out_kernel<<<dim3((BB * TT) / 64, OO / 64), 256>>>(s_out, Wout, bout, o_out);
}

// round 14
// speedup vs baseline: 2.4026x; 2.4026x over previous
#include <cuda_runtime.h>
#include <cuda_bf16.h>
#include <math.h>

#define TT  512
#define BB  64
#define DIN 256
#define NN  1024
#define OO  128

// ---------------- device scratch (no cudaMalloc allowed) ----------------
__device__ float    g_xw[(TT - 1) * BB * NN];   // [t][b][n], t = 0..510 feeds step t+1
__device__ float    g_sbuf[4 * NN * BB];        // 4-deep ring, [slot][n][b]
__device__ float    g_part[16 * 8 * 4096];      // [ntile][src_kq][b*64+c]
__device__ unsigned g_cnt[16 * 8];              // per-ntile partials-published counter (32B pad)
__device__ unsigned g_done[16 * 8];             // per-ntile s-written counter (32B pad)

// ---------------- sync helpers ----------------
__device__ __forceinline__ unsigned ld_acq(const unsigned* p) {
    unsigned v;
    asm volatile("ld.acquire.gpu.u32 %0, [%1];" : "=r"(v) : "l"(p));
    return v;
}
// bounded-backoff spin on monotonic counter (cannot deadlock).
// ONLY EVER CALLED BY ONE THREAD PER BLOCK (then __syncthreads) — many-thread
// polling saturates the LTS and has caused watchdog kills (R4/R5/R11).
__device__ __forceinline__ void wait_ge(const unsigned* p, unsigned tgt) {
    #pragma unroll 1
    for (int i = 0; i < 32; i++) {
        if (ld_acq(p) >= tgt) return;
    }
    unsigned ns = 32;
    #pragma unroll 1
    while (ld_acq(p) < tgt) {
        __nanosleep(ns);
        if (ns < 128) ns <<= 1;
    }
}
// wait two monotonic counters; polls both per round trip
__device__ __forceinline__ void wait2_ge(const unsigned* a, const unsigned* b,
                                         unsigned tgt) {
    #pragma unroll 1
    for (int i = 0; i < 32; i++) {
        unsigned va = ld_acq(a), vb = ld_acq(b);
        if (va >= tgt && vb >= tgt) return;
    }
    unsigned ns = 32;
    #pragma unroll 1
    while (true) {
        unsigned va = ld_acq(a), vb = ld_acq(b);
        if (va >= tgt && vb >= tgt) return;
        __nanosleep(ns);
        if (ns < 128) ns <<= 1;
    }
}

// packed fp32x2 FMA: d = a*b + d (lane-wise fp32, exact FFMA numerics)
__device__ __forceinline__ void ffma2(unsigned long long& d,
                                      unsigned long long a, unsigned long long b) {
    asm("fma.rn.f32x2 %0, %1, %2, %0;" : "+l"(d) : "l"(a), "l"(b));
}

// ---------------- init: reset counters, zero s[:,0,:] ----------------
__global__ void init_kernel(float* __restrict__ sout) {
    int idx = blockIdx.x * blockDim.x + threadIdx.x;
    if (idx < 16 * 8) { g_cnt[idx] = 0; g_done[idx] = 0; }
    if (idx < NN * BB) {
        g_sbuf[idx] = 0.0f;                          // ring slot 0 = state t=0
        int b = idx / NN, n = idx % NN;
        sout[((size_t)b * TT + 0) * NN + n] = 0.0f;  // s[:,0,:] = 0
    }
}

// ---------------- XW = X[:,t,:] @ Win, stored [t][b][n] ----------------
__global__ void xw_kernel(const float* __restrict__ X, const float* __restrict__ Win) {
    const int t  = blockIdx.x;          // 0..510
    const int c0 = blockIdx.y * 64;
    __shared__ float xs[16][BB];        // [d][b]
    __shared__ float ws[16][64];        // [d][c]
    const int tid = threadIdx.x;
    const int r0 = (tid & 15) * 4;
    const int cc = (tid >> 4) * 4;
    float acc[4][4] = {};

    for (int d0 = 0; d0 < DIN; d0 += 16) {
        {
            int b  = tid & 63;
            int d4 = (tid >> 6) * 4;
            float4 xv = *(const float4*)&X[((size_t)b * TT + t) * DIN + d0 + d4];
            xs[d4 + 0][b] = xv.x; xs[d4 + 1][b] = xv.y;
            xs[d4 + 2][b] = xv.z; xs[d4 + 3][b] = xv.w;
        }
        {
            int dr = tid >> 4;
            int c4 = (tid & 15) * 4;
            *(float4*)&ws[dr][c4] = *(const float4*)&Win[(size_t)(d0 + dr) * NN + c0 + c4];
        }
        __syncthreads();
        #pragma unroll
        for (int d = 0; d < 16; d++) {
            float4 a = *(const float4*)&xs[d][r0];
            float4 w = *(const float4*)&ws[d][cc];
            acc[0][0] += a.x * w.x; acc[0][1] += a.x * w.y; acc[0][2] += a.x * w.z; acc[0][3] += a.x * w.w;
            acc[1][0] += a.y * w.x; acc[1][1] += a.y * w.y; acc[1][2] += a.y * w.z; acc[1][3] += a.y * w.w;
            acc[2][0] += a.z * w.x; acc[2][1] += a.z * w.y; acc[2][2] += a.z * w.z; acc[2][3] += a.z * w.w;
            acc[3][0] += a.w * w.x; acc[3][1] += a.w * w.y; acc[3][2] += a.w * w.z; acc[3][3] += a.w * w.w;
        }
        __syncthreads();
    }
    #pragma unroll
    for (int i = 0; i < 4; i++) {
        *(float4*)&g_xw[((size_t)t * BB + r0 + i) * NN + c0 + cc] =
            make_float4(acc[i][0], acc[i][1], acc[i][2], acc[i][3]);
    }
}

// ---------------- persistent recurrence kernel ----------------
// 128 blocks x 128 threads, 1 block/SM. block = (ntile X 0..15, kq 0..7).
// Block GEMM tile: 64b x 64c over K rows [kq*128, +128). Thread tile 4b x 8c.
// All 8 blocks of a ntile publish partials; each finalizes its own 8-col slice.
// All gpu-scope waits: tid0 polls single counters, then __syncthreads.
// dynamic smem: wsm float[128][128] dup (64KB) | ssm float[2][32*64] (16KB)
#define RNN_SMEM (65536 + 16384)

__global__ void __launch_bounds__(128, 1) rnn_kernel(const float* __restrict__ W,
                                                     float* __restrict__ sout) {
    extern __shared__ char smem_raw[];
    float* wsm = (float*)smem_raw;                 // [k(128)][128 = 64 cols dup (w,w)]
    float* ssm = (float*)(smem_raw + 65536);       // [buf(2)][k(32)*b(64)]

    const int bx  = blockIdx.x;
    const int X   = bx >> 3;            // ntile 0..15 (64 cols)
    const int kq  = bx & 7;             // K-split 0..7 (128 rows)
    const int c0  = X * 64;
    const int kbase = kq * 128;
    const int tid = threadIdx.x;
    const int bg  = tid & 15;           // b-group: rows bg*4..+3
    const int ng  = tid >> 4;           // c-group 0..7: cols ng*8..+7

    // ---- preload W slice (128 k x 64 c), duplicated pairs ----
    #pragma unroll 1
    for (int i = tid; i < 128 * 16; i += 128) {
        int k = i >> 4, g = i & 15;     // g = group of 4 cols
        float4 w = *(const float4*)&W[(size_t)(kbase + k) * NN + c0 + g * 4];
        float* d = &wsm[k * 128 + g * 8];
        *(float4*)&d[0] = make_float4(w.x, w.x, w.y, w.y);
        *(float4*)&d[4] = make_float4(w.z, w.z, w.w, w.w);
    }
    __syncthreads();

    const int n_left  = 2 * kq;         // ntile producing K rows [kq*128, +64)
    const int n_right = 2 * kq + 1;     // ntile producing [kq*128+64, +64)

    for (int t = 1; t < TT; t++) {
        // ---- head wait: producer ntiles of our K-range done with step t-1 ----
        if (tid == 0) {
            wait2_ge(&g_done[n_left * 8], &g_done[n_right * 8], 8u * (unsigned)(t - 1));
        }
        __syncthreads();

        const float* __restrict__ sprev =
            &g_sbuf[((t - 1) & 3) * (NN * BB) + (size_t)kbase * BB];

        unsigned long long ap[8][2];    // [col][b-pair]
        #pragma unroll
        for (int j = 0; j < 8; j++) { ap[j][0] = 0ull; ap[j][1] = 0ull; }

        // prologue: chunk 0 (32 k x 64 b = 8KB) into buf 0
        {
            const float4* sv = (const float4*)sprev;
            float4* d = (float4*)ssm;
            #pragma unroll
            for (int i = 0; i < 4; i++) d[tid + 128 * i] = sv[tid + 128 * i];
        }
        __syncthreads();

        #pragma unroll 1
        for (int ch = 0; ch < 4; ch++) {
            const int buf = ch & 1;
            float4 pfs[4];
            if (ch < 3) {
                const float4* sv = (const float4*)(sprev + (size_t)(ch + 1) * 32 * BB);
                #pragma unroll
                for (int i = 0; i < 4; i++) pfs[i] = sv[tid + 128 * i];
            }
            const float* sb = ssm + buf * (32 * 64);
            const float* wr = wsm + (size_t)ch * 32 * 128 + ng * 16;
            #pragma unroll
            for (int k = 0; k < 32; k++) {
                ulonglong2 a2 = *(const ulonglong2*)&sb[k * 64 + bg * 4];  // (s0,s1),(s2,s3)
                #pragma unroll
                for (int j4 = 0; j4 < 4; j4++) {
                    ulonglong2 b2 = *(const ulonglong2*)&wr[k * 128 + j4 * 4]; // (w,w),(w',w')
                    ffma2(ap[j4 * 2 + 0][0], a2.x, b2.x);
                    ffma2(ap[j4 * 2 + 0][1], a2.y, b2.x);
                    ffma2(ap[j4 * 2 + 1][0], a2.x, b2.y);
                    ffma2(ap[j4 * 2 + 1][1], a2.y, b2.y);
                }
            }
            if (ch < 3) {
                float4* d = (float4*)(ssm + (buf ^ 1) * (32 * 64));
                #pragma unroll
                for (int i = 0; i < 4; i++) d[tid + 128 * i] = pfs[i];
                __syncthreads();
            }
        }

        // ---- g_part WAR guard, overlapped behind the GEMM (usually instant):
        //      all siblings of ntile X must have finished step t-1 finalize ----
        if (tid == 0) wait_ge(&g_done[X * 8], 8u * (unsigned)(t - 1));
        __syncthreads();

        // ---- publish partial tile (64x64) ----
        {
            float* p = &g_part[((size_t)X * 8 + kq) * 4096];
            #pragma unroll
            for (int i = 0; i < 4; i++) {           // b row = bg*4 + i
                int hi = i >> 1;
                float4 v0, v1;
                float2 u;
                u = *(float2*)&ap[0][hi]; v0.x = (i & 1) ? u.y : u.x;
                u = *(float2*)&ap[1][hi]; v0.y = (i & 1) ? u.y : u.x;
                u = *(float2*)&ap[2][hi]; v0.z = (i & 1) ? u.y : u.x;
                u = *(float2*)&ap[3][hi]; v0.w = (i & 1) ? u.y : u.x;
                u = *(float2*)&ap[4][hi]; v1.x = (i & 1) ? u.y : u.x;
                u = *(float2*)&ap[5][hi]; v1.y = (i & 1) ? u.y : u.x;
                u = *(float2*)&ap[6][hi]; v1.z = (i & 1) ? u.y : u.x;
                u = *(float2*)&ap[7][hi]; v1.w = (i & 1) ? u.y : u.x;
                int b = bg * 4 + i;
                *(float4*)&p[b * 64 + ng * 8 + 0] = v0;
                *(float4*)&p[b * 64 + ng * 8 + 4] = v1;
            }
        }
        __threadfence();
        __syncthreads();
        if (tid == 0) atomicAdd(&g_cnt[X * 8], 1u);

        // ---- finalize our 8-col slice ----
        const int bfin = tid >> 1;                      // b 0..63
        const int cloc = kq * 8 + (tid & 1) * 4;        // col within ntile
        // prefetch xw operand (g_xw constant during rnn) to overlap the wait
        float4 xv = *(const float4*)&g_xw[((size_t)(t - 1) * BB + bfin) * NN + c0 + cloc];
        if (tid == 0) wait_ge(&g_cnt[X * 8], 8u * (unsigned)t);
        __syncthreads();
        {
            float4 sum = make_float4(0.f, 0.f, 0.f, 0.f);
            #pragma unroll
            for (int src = 0; src < 8; src++) {
                float4 v = *(const float4*)&g_part[((size_t)X * 8 + src) * 4096 + bfin * 64 + cloc];
                sum.x += v.x; sum.y += v.y; sum.z += v.z; sum.w += v.w;
            }
            float4 sn;
            sn.x = tanhf(sum.x + xv.x);
            sn.y = tanhf(sum.y + xv.y);
            sn.z = tanhf(sum.z + xv.z);
            sn.w = tanhf(sum.w + xv.w);
            // state ring [slot][n][b]
            float* sb = &g_sbuf[(t & 3) * (NN * BB)];
            sb[(size_t)(c0 + cloc + 0) * BB + bfin] = sn.x;
            sb[(size_t)(c0 + cloc + 1) * BB + bfin] = sn.y;
            sb[(size_t)(c0 + cloc + 2) * BB + bfin] = sn.z;
            sb[(size_t)(c0 + cloc + 3) * BB + bfin] = sn.w;
            __threadfence();
            __syncthreads();
            if (tid == 0) atomicAdd(&g_done[X * 8], 1u);
            // sout write AFTER the done-counter: nothing in rnn reads sout;
            // kernel-end ordering guarantees visibility for out_kernel.
            *(float4*)&sout[((size_t)bfin * TT + t) * NN + c0 + cloc] = sn;
        }
    }
}

// ---------------- out = s @ Wout + bout ----------------
__global__ void out_kernel(const float* __restrict__ s, const float* __restrict__ Wout,
                           const float* __restrict__ bout, float* __restrict__ out) {
    const int m0 = blockIdx.x * 64;
    const int c0 = blockIdx.y * 64;
    __shared__ float as[16][64];        // [k][m]
    __shared__ float ws[16][64];        // [k][o]
    const int tid = threadIdx.x;
    const int r0 = (tid & 15) * 4;
    const int cc = (tid >> 4) * 4;
    float acc[4][4] = {};

    for (int k0 = 0; k0 < NN; k0 += 16) {
        {
            int m  = tid & 63;
            int k4 = (tid >> 6) * 4;
            float4 v = *(const float4*)&s[(size_t)(m0 + m) * NN + k0 + k4];
            as[k4 + 0][m] = v.x; as[k4 + 1][m] = v.y;
            as[k4 + 2][m] = v.z; as[k4 + 3][m] = v.w;
        }
        {
            int kr = tid >> 4;
            int c4 = (tid & 15) * 4;
            *(float4*)&ws[kr][c4] = *(const float4*)&Wout[(size_t)(k0 + kr) * OO + c0 + c4];
        }
        __syncthreads();
        #pragma unroll
        for (int k = 0; k < 16; k++) {
            float4 a = *(const float4*)&as[k][r0];
            float4 w = *(const float4*)&ws[k][cc];
            acc[0][0] += a.x * w.x; acc[0][1] += a.x * w.y; acc[0][2] += a.x * w.z; acc[0][3] += a.x * w.w;
            acc[1][0] += a.y * w.x; acc[1][1] += a.y * w.y; acc[1][2] += a.y * w.z; acc[1][3] += a.y * w.w;
            acc[2][0] += a.z * w.x; acc[2][1] += a.z * w.y; acc[2][2] += a.z * w.z; acc[2][3] += a.z * w.w;
            acc[3][0] += a.w * w.x; acc[3][1] += a.w * w.y; acc[3][2] += a.w * w.z; acc[3][3] += a.w * w.w;
        }
        __syncthreads();
    }
    float4 bv = *(const float4*)&bout[c0 + cc];
    #pragma unroll
    for (int i = 0; i < 4; i++) {
        float4 v = make_float4(acc[i][0] + bv.x, acc[i][1] + bv.y,
                               acc[i][2] + bv.z, acc[i][3] + bv.w);
        *(float4*)&out[(size_t)(m0 + r0 + i) * OO + c0 + cc] = v;
    }
}

// ---------------- launch (stateless) ----------------
extern "C" void kernel_launch(void* const* d_in, const int* in_sizes, int n_in,
                              void* d_out, int out_size) {
    const float* X    = (const float*)d_in[0];  // [B,T,DIN]
    const float* Win  = (const float*)d_in[1];  // [DIN,N]
    const float* W    = (const float*)d_in[2];  // [N,N]
    const float* Wout = (const float*)d_in[3];  // [N,O]
    const float* bout = (const float*)d_in[4];  // [O]

    float* s_out = (float*)d_out;                            // [B,T,N]
    float* o_out = (float*)d_out + (size_t)BB * TT * NN;     // [B,T,O]

    cudaFuncSetAttribute(rnn_kernel, cudaFuncAttributeMaxDynamicSharedMemorySize, RNN_SMEM);

    init_kernel<<<256, 256>>>(s_out);
    xw_kernel<<<dim3(TT - 1, 16), 256>>>(X, Win);
    rnn_kernel<<<128, 128, RNN_SMEM>>>(W, s_out);
    out_kernel<<<dim3((BB * TT) / 64, OO / 64), 256>>>(s_out, Wout, bout, o_out);
}

// round 17
// speedup vs baseline: 2.4673x; 1.0269x over previous
#include <cuda_runtime.h>
#include <cuda_bf16.h>
#include <math.h>

#define TT  512
#define BB  64
#define DIN 256
#define NN  1024
#define OO  128

// ---------------- device scratch (no cudaMalloc allowed) ----------------
__device__ float    g_xw[(TT - 1) * BB * NN];   // [t][b][n], t = 0..510 feeds step t+1
__device__ float    g_sbuf[4 * NN * BB];        // 4-deep ring, [slot][n][b]
__device__ float    g_part[2][16 * 8 * 4096];   // parity-buffered [t&1][ntile][src_kq][b*64+c]
__device__ unsigned g_cnt[16 * 8];              // per-ntile partials-published counter (32B pad)
__device__ unsigned g_done[16 * 8];             // per-ntile s-written counter (32B pad)

// ---------------- sync helpers ----------------
__device__ __forceinline__ unsigned ld_acq(const unsigned* p) {
    unsigned v;
    asm volatile("ld.acquire.gpu.u32 %0, [%1];" : "=r"(v) : "l"(p));
    return v;
}
// bounded-backoff spin on monotonic counter (cannot deadlock).
// ONLY EVER CALLED BY ONE THREAD PER BLOCK (then __syncthreads) — many-thread
// polling saturates the LTS and has caused watchdog kills (R4/R5/R11).
__device__ __forceinline__ void wait_ge(const unsigned* p, unsigned tgt) {
    #pragma unroll 1
    for (int i = 0; i < 32; i++) {
        if (ld_acq(p) >= tgt) return;
    }
    unsigned ns = 32;
    #pragma unroll 1
    while (ld_acq(p) < tgt) {
        __nanosleep(ns);
        if (ns < 128) ns <<= 1;
    }
}
// wait two monotonic counters; polls both per round trip
__device__ __forceinline__ void wait2_ge(const unsigned* a, const unsigned* b,
                                         unsigned tgt) {
    #pragma unroll 1
    for (int i = 0; i < 32; i++) {
        unsigned va = ld_acq(a), vb = ld_acq(b);
        if (va >= tgt && vb >= tgt) return;
    }
    unsigned ns = 32;
    #pragma unroll 1
    while (true) {
        unsigned va = ld_acq(a), vb = ld_acq(b);
        if (va >= tgt && vb >= tgt) return;
        __nanosleep(ns);
        if (ns < 128) ns <<= 1;
    }
}

// packed fp32x2 FMA: d = a*b + d (lane-wise fp32, exact FFMA numerics)
__device__ __forceinline__ void ffma2(unsigned long long& d,
                                      unsigned long long a, unsigned long long b) {
    asm("fma.rn.f32x2 %0, %1, %2, %0;" : "+l"(d) : "l"(a), "l"(b));
}

// fast tanh: (e^{2x}-1)/(e^{2x}+1), clamped; rel err ~1e-6, budget 1e-3
__device__ __forceinline__ float ftanh(float x) {
    float ax = fminf(fmaxf(x, -15.f), 15.f);
    float e = __expf(2.f * ax);
    return __fdividef(e - 1.f, e + 1.f);
}

// ---------------- init: reset counters, zero s[:,0,:] ----------------
__global__ void init_kernel(float* __restrict__ sout) {
    int idx = blockIdx.x * blockDim.x + threadIdx.x;
    if (idx < 16 * 8) { g_cnt[idx] = 0; g_done[idx] = 0; }
    if (idx < NN * BB) {
        g_sbuf[idx] = 0.0f;                          // ring slot 0 = state t=0
        int b = idx / NN, n = idx % NN;
        sout[((size_t)b * TT + 0) * NN + n] = 0.0f;  // s[:,0,:] = 0
    }
}

// ---------------- XW = X[:,t,:] @ Win, stored [t][b][n] ----------------
__global__ void xw_kernel(const float* __restrict__ X, const float* __restrict__ Win) {
    const int t  = blockIdx.x;          // 0..510
    const int c0 = blockIdx.y * 64;
    __shared__ float xs[16][BB];        // [d][b]
    __shared__ float ws[16][64];        // [d][c]
    const int tid = threadIdx.x;
    const int r0 = (tid & 15) * 4;
    const int cc = (tid >> 4) * 4;
    float acc[4][4] = {};

    for (int d0 = 0; d0 < DIN; d0 += 16) {
        {
            int b  = tid & 63;
            int d4 = (tid >> 6) * 4;
            float4 xv = *(const float4*)&X[((size_t)b * TT + t) * DIN + d0 + d4];
            xs[d4 + 0][b] = xv.x; xs[d4 + 1][b] = xv.y;
            xs[d4 + 2][b] = xv.z; xs[d4 + 3][b] = xv.w;
        }
        {
            int dr = tid >> 4;
            int c4 = (tid & 15) * 4;
            *(float4*)&ws[dr][c4] = *(const float4*)&Win[(size_t)(d0 + dr) * NN + c0 + c4];
        }
        __syncthreads();
        #pragma unroll
        for (int d = 0; d < 16; d++) {
            float4 a = *(const float4*)&xs[d][r0];
            float4 w = *(const float4*)&ws[d][cc];
            acc[0][0] += a.x * w.x; acc[0][1] += a.x * w.y; acc[0][2] += a.x * w.z; acc[0][3] += a.x * w.w;
            acc[1][0] += a.y * w.x; acc[1][1] += a.y * w.y; acc[1][2] += a.y * w.z; acc[1][3] += a.y * w.w;
            acc[2][0] += a.z * w.x; acc[2][1] += a.z * w.y; acc[2][2] += a.z * w.z; acc[2][3] += a.z * w.w;
            acc[3][0] += a.w * w.x; acc[3][1] += a.w * w.y; acc[3][2] += a.w * w.z; acc[3][3] += a.w * w.w;
        }
        __syncthreads();
    }
    #pragma unroll
    for (int i = 0; i < 4; i++) {
        *(float4*)&g_xw[((size_t)t * BB + r0 + i) * NN + c0 + cc] =
            make_float4(acc[i][0], acc[i][1], acc[i][2], acc[i][3]);
    }
}

// ---------------- persistent recurrence kernel ----------------
// 128 blocks x 128 threads, 1 block/SM. block = (ntile X 0..15, kq 0..7).
// Block GEMM tile: 64b x 64c over K rows [kq*128, +128). Thread tile 4b x 8c.
// All 8 blocks of a ntile publish parity-buffered partials; each finalizes its
// own 8-col slice. All gpu-scope waits: tid0 polls counters, then __syncthreads.
// dynamic smem: wsm float[128][128] dup (64KB) | ssm float[2][32*64] (16KB)
#define RNN_SMEM (65536 + 16384)

__global__ void __launch_bounds__(128, 1) rnn_kernel(const float* __restrict__ W,
                                                     float* __restrict__ sout) {
    extern __shared__ char smem_raw[];
    float* wsm = (float*)smem_raw;                 // [k(128)][128 = 64 cols dup (w,w)]
    float* ssm = (float*)(smem_raw + 65536);       // [buf(2)][k(32)*b(64)]

    const int bx  = blockIdx.x;
    const int X   = bx >> 3;            // ntile 0..15 (64 cols)
    const int kq  = bx & 7;             // K-split 0..7 (128 rows)
    const int c0  = X * 64;
    const int kbase = kq * 128;
    const int tid = threadIdx.x;
    const int bg  = tid & 15;           // b-group: rows bg*4..+3
    const int ng  = tid >> 4;           // c-group 0..7: cols ng*8..+7

    // ---- preload W slice (128 k x 64 c), duplicated pairs ----
    #pragma unroll 1
    for (int i = tid; i < 128 * 16; i += 128) {
        int k = i >> 4, g = i & 15;     // g = group of 4 cols
        float4 w = *(const float4*)&W[(size_t)(kbase + k) * NN + c0 + g * 4];
        float* d = &wsm[k * 128 + g * 8];
        *(float4*)&d[0] = make_float4(w.x, w.x, w.y, w.y);
        *(float4*)&d[4] = make_float4(w.z, w.z, w.w, w.w);
    }
    __syncthreads();

    const int n_left  = 2 * kq;         // ntile producing K rows [kq*128, +64)
    const int n_right = 2 * kq + 1;     // ntile producing [kq*128+64, +64)

    for (int t = 1; t < TT; t++) {
        // ---- head wait: producer ntiles of our K-range done with step t-1 ----
        if (tid == 0) {
            wait2_ge(&g_done[n_left * 8], &g_done[n_right * 8], 8u * (unsigned)(t - 1));
        }
        __syncthreads();

        const float* __restrict__ sprev =
            &g_sbuf[((t - 1) & 3) * (NN * BB) + (size_t)kbase * BB];

        unsigned long long ap[8][2];    // [col][b-pair]
        #pragma unroll
        for (int j = 0; j < 8; j++) { ap[j][0] = 0ull; ap[j][1] = 0ull; }

        // prologue: chunk 0 (32 k x 64 b = 8KB) into buf 0
        {
            const float4* sv = (const float4*)sprev;
            float4* d = (float4*)ssm;
            #pragma unroll
            for (int i = 0; i < 4; i++) d[tid + 128 * i] = sv[tid + 128 * i];
        }
        __syncthreads();

        #pragma unroll 1
        for (int ch = 0; ch < 4; ch++) {
            const int buf = ch & 1;
            float4 pfs[4];
            if (ch < 3) {
                const float4* sv = (const float4*)(sprev + (size_t)(ch + 1) * 32 * BB);
                #pragma unroll
                for (int i = 0; i < 4; i++) pfs[i] = sv[tid + 128 * i];
            }
            const float* sb = ssm + buf * (32 * 64);
            const float* wr = wsm + (size_t)ch * 32 * 128 + ng * 16;
            #pragma unroll
            for (int k = 0; k < 32; k++) {
                ulonglong2 a2 = *(const ulonglong2*)&sb[k * 64 + bg * 4];  // (s0,s1),(s2,s3)
                #pragma unroll
                for (int j4 = 0; j4 < 4; j4++) {
                    ulonglong2 b2 = *(const ulonglong2*)&wr[k * 128 + j4 * 4]; // (w,w),(w',w')
                    ffma2(ap[j4 * 2 + 0][0], a2.x, b2.x);
                    ffma2(ap[j4 * 2 + 0][1], a2.y, b2.x);
                    ffma2(ap[j4 * 2 + 1][0], a2.x, b2.y);
                    ffma2(ap[j4 * 2 + 1][1], a2.y, b2.y);
                }
            }
            if (ch < 3) {
                float4* d = (float4*)(ssm + (buf ^ 1) * (32 * 64));
                #pragma unroll
                for (int i = 0; i < 4; i++) d[tid + 128 * i] = pfs[i];
                __syncthreads();
            }
        }

        // ---- publish partial tile (64x64) into parity slot.
        //      No WAR wait: publish(t) ≻ finalize(t-1) ≻ [g_cnt ≥ 8(t-1)]
        //      ≻ siblings' publish(t-1) ≻ their finalize(t-2) reads of this slot. ----
        {
            float* p = &g_part[t & 1][((size_t)X * 8 + kq) * 4096];
            #pragma unroll
            for (int i = 0; i < 4; i++) {           // b row = bg*4 + i
                int hi = i >> 1;
                float4 v0, v1;
                float2 u;
                u = *(float2*)&ap[0][hi]; v0.x = (i & 1) ? u.y : u.x;
                u = *(float2*)&ap[1][hi]; v0.y = (i & 1) ? u.y : u.x;
                u = *(float2*)&ap[2][hi]; v0.z = (i & 1) ? u.y : u.x;
                u = *(float2*)&ap[3][hi]; v0.w = (i & 1) ? u.y : u.x;
                u = *(float2*)&ap[4][hi]; v1.x = (i & 1) ? u.y : u.x;
                u = *(float2*)&ap[5][hi]; v1.y = (i & 1) ? u.y : u.x;
                u = *(float2*)&ap[6][hi]; v1.z = (i & 1) ? u.y : u.x;
                u = *(float2*)&ap[7][hi]; v1.w = (i & 1) ? u.y : u.x;
                int b = bg * 4 + i;
                *(float4*)&p[b * 64 + ng * 8 + 0] = v0;
                *(float4*)&p[b * 64 + ng * 8 + 4] = v1;
            }
        }
        __threadfence();
        __syncthreads();
        if (tid == 0) atomicAdd(&g_cnt[X * 8], 1u);

        // ---- finalize our 8-col slice ----
        const int bfin = tid >> 1;                      // b 0..63
        const int cloc = kq * 8 + (tid & 1) * 4;        // col within ntile
        // prefetch xw operand (g_xw constant during rnn) to overlap the wait
        float4 xv = *(const float4*)&g_xw[((size_t)(t - 1) * BB + bfin) * NN + c0 + cloc];
        if (tid == 0) wait_ge(&g_cnt[X * 8], 8u * (unsigned)t);
        __syncthreads();
        {
            const float* pp = &g_part[t & 1][(size_t)X * 8 * 4096 + bfin * 64 + cloc];
            float4 sum = make_float4(0.f, 0.f, 0.f, 0.f);
            #pragma unroll
            for (int src = 0; src < 8; src++) {
                float4 v = *(const float4*)&pp[(size_t)src * 4096];
                sum.x += v.x; sum.y += v.y; sum.z += v.z; sum.w += v.w;
            }
            float4 sn;
            sn.x = ftanh(sum.x + xv.x);
            sn.y = ftanh(sum.y + xv.y);
            sn.z = ftanh(sum.z + xv.z);
            sn.w = ftanh(sum.w + xv.w);
            // state ring [slot][n][b]
            float* sb = &g_sbuf[(t & 3) * (NN * BB)];
            sb[(size_t)(c0 + cloc + 0) * BB + bfin] = sn.x;
            sb[(size_t)(c0 + cloc + 1) * BB + bfin] = sn.y;
            sb[(size_t)(c0 + cloc + 2) * BB + bfin] = sn.z;
            sb[(size_t)(c0 + cloc + 3) * BB + bfin] = sn.w;
            __threadfence();
            __syncthreads();
            if (tid == 0) atomicAdd(&g_done[X * 8], 1u);
            // sout write AFTER the done-counter: nothing in rnn reads sout;
            // kernel-end ordering guarantees visibility for out_kernel.
            *(float4*)&sout[((size_t)bfin * TT + t) * NN + c0 + cloc] = sn;
        }
    }
}

// ---------------- out = s @ Wout + bout ----------------
__global__ void out_kernel(const float* __restrict__ s, const float* __restrict__ Wout,
                           const float* __restrict__ bout, float* __restrict__ out) {
    const int m0 = blockIdx.x * 64;
    const int c0 = blockIdx.y * 64;
    __shared__ float as[16][64];        // [k][m]
    __shared__ float ws[16][64];        // [k][o]
    const int tid = threadIdx.x;
    const int r0 = (tid & 15) * 4;
    const int cc = (tid >> 4) * 4;
    float acc[4][4] = {};

    for (int k0 = 0; k0 < NN; k0 += 16) {
        {
            int m  = tid & 63;
            int k4 = (tid >> 6) * 4;
            float4 v = *(const float4*)&s[(size_t)(m0 + m) * NN + k0 + k4];
            as[k4 + 0][m] = v.x; as[k4 + 1][m] = v.y;
            as[k4 + 2][m] = v.z; as[k4 + 3][m] = v.w;
        }
        {
            int kr = tid >> 4;
            int c4 = (tid & 15) * 4;
            *(float4*)&ws[kr][c4] = *(const float4*)&Wout[(size_t)(k0 + kr) * OO + c0 + c4];
        }
        __syncthreads();
        #pragma unroll
        for (int k = 0; k < 16; k++) {
            float4 a = *(const float4*)&as[k][r0];
            float4 w = *(const float4*)&ws[k][cc];
            acc[0][0] += a.x * w.x; acc[0][1] += a.x * w.y; acc[0][2] += a.x * w.z; acc[0][3] += a.x * w.w;
            acc[1][0] += a.y * w.x; acc[1][1] += a.y * w.y; acc[1][2] += a.y * w.z; acc[1][3] += a.y * w.w;
            acc[2][0] += a.z * w.x; acc[2][1] += a.z * w.y; acc[2][2] += a.z * w.z; acc[2][3] += a.z * w.w;
            acc[3][0] += a.w * w.x; acc[3][1] += a.w * w.y; acc[3][2] += a.w * w.z; acc[3][3] += a.w * w.w;
        }
        __syncthreads();
    }
    float4 bv = *(const float4*)&bout[c0 + cc];
    #pragma unroll
    for (int i = 0; i < 4; i++) {
        float4 v = make_float4(acc[i][0] + bv.x, acc[i][1] + bv.y,
                               acc[i][2] + bv.z, acc[i][3] + bv.w);
        *(float4*)&out[(size_t)(m0 + r0 + i) * OO + c0 + cc] = v;
    }
}

// ---------------- launch (stateless) ----------------
extern "C" void kernel_launch(void* const* d_in, const int* in_sizes, int n_in,
                              void* d_out, int out_size) {
    const float* X    = (const float*)d_in[0];  // [B,T,DIN]
    const float* Win  = (const float*)d_in[1];  // [DIN,N]
    const float* W    = (const float*)d_in[2];  // [N,N]
    const float* Wout = (const float*)d_in[3];  // [N,O]
    const float* bout = (const float*)d_in[4];  // [O]

    float* s_out = (float*)d_out;                            // [B,T,N]
    float* o_out = (float*)d_out + (size_t)BB * TT * NN;     // [B,T,O]

    cudaFuncSetAttribute(rnn_kernel, cudaFuncAttributeMaxDynamicSharedMemorySize, RNN_SMEM);

    init_kernel<<<256, 256>>>(s_out);
    xw_kernel<<<dim3(TT - 1, 16), 256>>>(X, Win);
    rnn_kernel<<<128, 128, RNN_SMEM>>>(W, s_out);
    out_kernel<<<dim3((BB * TT) / 64, OO / 64), 256>>>(s_out, Wout, bout, o_out);
}